// round 14
// baseline (speedup 1.0000x reference)
#include <cuda_runtime.h>

#define L 2048
#define B 32
#define H 1024
#define H4 256
#define NB 148
#define NT 1024

// Scratch (allocation-free rule: __device__ globals)
__device__ float g_vpart[64][B][H];      // 8 MB partials (16 g each)
__device__ float g_vq[4][B][H];          // 512 KB quarter-reduced v
__device__ float g_v[B][H];              // 128 KB final v (L1-resident in P3)
__device__ float g_energy[B][L];         // 256 KB energies
__device__ unsigned g_maxu[B];           // monotone-encoded per-b max
__device__ unsigned g_bar;               // monotonic grid barrier counter

__device__ __forceinline__ unsigned enc_f(float x) {
    unsigned u = __float_as_uint(x);
    return (x >= 0.f) ? (u | 0x80000000u) : ~u;
}
__device__ __forceinline__ float dec_f(unsigned e) {
    return (e & 0x80000000u) ? __uint_as_float(e ^ 0x80000000u)
                             : __uint_as_float(~e);
}

// Software grid barrier: monotonic counter, no reset across replays.
__device__ __forceinline__ void grid_sync() {
    __syncthreads();
    if (threadIdx.x == 0) {
        __threadfence();
        const unsigned old = atomicAdd(&g_bar, 1u);
        const unsigned tgt = (old / NB + 1u) * NB;
        while (*(volatile unsigned*)&g_bar < tgt) __nanosleep(64);
        __threadfence();
    }
    __syncthreads();
}

__global__ void __launch_bounds__(NT, 1)
fused_attn(const float* __restrict__ hidden,
           const float* __restrict__ enc,
           const float* __restrict__ W,
           const int*   __restrict__ lengths,
           float* __restrict__ out) {
    const int tid = threadIdx.x;
    const int bid = blockIdx.x;

    __shared__ float hsh[4][4][16];      // P1 hidden stage (1 KB)
    __shared__ float red_s[32];          // P4 reduction

    if (bid == 0 && tid < B) g_maxu[tid] = 0u;   // encoded -inf (pre-sync)

    // ---------------- Phase 1: v partials ----------------
    // 512 groups = 64 g-slices x 8 b-quads; blocks 0..127, 4 groups each.
    if (bid < 128) {
        if (tid < 256) {   // stage hidden: 4 lg x 4 b x 16 g
            const int lg = tid >> 6, j = (tid >> 4) & 3, k = tid & 15;
            const int grp = bid * 4 + lg;
            const int gs = grp >> 3, bq = grp & 7;
            hsh[lg][j][k] = hidden[(size_t)(bq * 4 + j) * H + gs * 16 + k];
        }
        __syncthreads();

        const int lg = tid >> 8, hq = tid & 255;
        const int grp = bid * 4 + lg;
        const int gs = grp >> 3, bq = grp & 7;
        const int g0 = gs * 16, b0 = bq * 4;
        const float4* __restrict__ W4 = (const float4*)W;

        float4 acc[4];
        #pragma unroll
        for (int j = 0; j < 4; j++) acc[j] = make_float4(0.f, 0.f, 0.f, 0.f);

        #pragma unroll
        for (int r = 0; r < 4; r++) {
            float4 w[4];
            #pragma unroll
            for (int i = 0; i < 4; i++)
                w[i] = W4[(size_t)(g0 + r * 4 + i) * H4 + hq];
            #pragma unroll
            for (int i = 0; i < 4; i++) {
                #pragma unroll
                for (int j = 0; j < 4; j++) {
                    const float hv = hsh[lg][j][r * 4 + i];
                    acc[j].x += w[i].x * hv; acc[j].y += w[i].y * hv;
                    acc[j].z += w[i].z * hv; acc[j].w += w[i].w * hv;
                }
            }
        }
        #pragma unroll
        for (int j = 0; j < 4; j++)
            *(float4*)&g_vpart[gs][b0 + j][hq * 4] = acc[j];
    }
    grid_sync();

    // ---------------- Phase 2a: quarter reduce ----------------
    {
        const int t = bid * NT + tid;
        if (t < 32768) {
            const int q = t >> 13, f = t & 8191;
            const int b = f >> 8, h4 = f & 255;
            const int p0 = q * 16;
            float4 s = make_float4(0.f, 0.f, 0.f, 0.f);
            #pragma unroll
            for (int r = 0; r < 4; r++) {
                float4 v[4];
                #pragma unroll
                for (int i = 0; i < 4; i++)
                    v[i] = *(const float4*)&g_vpart[p0 + r * 4 + i][b][h4 * 4];
                #pragma unroll
                for (int i = 0; i < 4; i++) {
                    s.x += v[i].x; s.y += v[i].y; s.z += v[i].z; s.w += v[i].w;
                }
            }
            *(float4*)&g_vq[q][b][h4 * 4] = s;
        }
    }
    grid_sync();

    // ---------------- Phase 2b: final reduce -> g_v ----------------
    {
        const int t = bid * NT + tid;
        if (t < 8192) {
            const int b = t >> 8, h4 = t & 255;
            float4 v[4];
            #pragma unroll
            for (int q = 0; q < 4; q++)
                v[q] = *(const float4*)&g_vq[q][b][h4 * 4];
            float4 s = make_float4(v[0].x + v[1].x + v[2].x + v[3].x,
                                   v[0].y + v[1].y + v[2].y + v[3].y,
                                   v[0].z + v[1].z + v[2].z + v[3].z,
                                   v[0].w + v[1].w + v[2].w + v[3].w);
            *(float4*)&g_v[b][h4 * 4] = s;
        }
    }
    grid_sync();

    // ---------------- Phase 3: energies (static bijective schedule) ----
    // Warp gw, iter k: b=(gw+k)&31, t=(gw>>5)+148k, rows (2t, 2t+1).
    // Bijective over all (b,t); each warp's ~7 pairs span 7 DIFFERENT b's,
    // so length-pruning (rows l>=len[b] never read; exact — masked to 0
    // downstream) removes work near-uniformly per warp. No syncs/atomics/
    // smem; v comes from g_v (fits in L1), len via one shfl.
    {
        const int lane = tid & 31;
        const int gw   = bid * 32 + (tid >> 5);    // 0..4735
        const int gw5  = gw >> 5;                  // 0..147
        const float4* __restrict__ enc4 = (const float4*)enc;
        const float4* __restrict__ gv4  = (const float4*)g_v;

        const int mylen = lengths[lane];           // lane-cached lengths

        #pragma unroll
        for (int k = 0; k < 7; k++) {
            const int t = gw5 + 148 * k;
            if (t >= 1024) break;
            const int b   = (gw + k) & 31;
            const int len = __shfl_sync(0xffffffffu, mylen, b);
            const int l0  = t * 2;
            if (l0 >= len) continue;               // warp-uniform skip
            const bool v1 = (l0 + 1 < len);

            const size_t ba = ((size_t)l0 * B + b) * H4;
            const size_t bb = ba + (size_t)B * H4;
            const float4* __restrict__ vb = gv4 + b * H4;

            float a0 = 0.f, a1 = 0.f;
            if (v1) {
                #pragma unroll
                for (int kk = 0; kk < 8; kk++) {
                    const float4 v  = vb[kk * 32 + lane];   // L1 hit
                    const float4 e0 = __ldcs(&enc4[ba + kk * 32 + lane]);
                    const float4 e1 = __ldcs(&enc4[bb + kk * 32 + lane]);
                    a0 += e0.x * v.x + e0.y * v.y + e0.z * v.z + e0.w * v.w;
                    a1 += e1.x * v.x + e1.y * v.y + e1.z * v.z + e1.w * v.w;
                }
            } else {
                #pragma unroll
                for (int kk = 0; kk < 8; kk++) {
                    const float4 v  = vb[kk * 32 + lane];
                    const float4 e0 = __ldcs(&enc4[ba + kk * 32 + lane]);
                    a0 += e0.x * v.x + e0.y * v.y + e0.z * v.z + e0.w * v.w;
                }
            }
            #pragma unroll
            for (int s = 16; s; s >>= 1) {
                a0 += __shfl_down_sync(0xffffffffu, a0, s);
                a1 += __shfl_down_sync(0xffffffffu, a1, s);
            }
            if (lane == 0) {
                g_energy[b][l0] = a0;
                float m = a0;
                if (v1) { g_energy[b][l0 + 1] = a1; m = fmaxf(m, a1); }
                atomicMax(&g_maxu[b], enc_f(m));   // max over valid only
            }
        }
    }
    grid_sync();

    // ---------------- Phase 4: masked softmax ----------------
    if (bid < B) {
        const int b   = bid;
        const int len = lengths[b];
        const int l0  = tid * 2;

        const float2 e = ((const float2*)&g_energy[b][0])[tid];
        const float mx = dec_f(g_maxu[b]);

        float x0 = (l0 + 0 < len) ? expf(e.x - mx) : 0.f;
        float x1 = (l0 + 1 < len) ? expf(e.y - mx) : 0.f;

        float sum = x0 + x1;
        #pragma unroll
        for (int s = 16; s; s >>= 1)
            sum += __shfl_xor_sync(0xffffffffu, sum, s);
        if ((tid & 31) == 0) red_s[tid >> 5] = sum;
        __syncthreads();
        if (tid < 32) {
            float m = red_s[tid];
            #pragma unroll
            for (int s = 16; s; s >>= 1)
                m += __shfl_xor_sync(0xffffffffu, m, s);
            if (tid == 0) red_s[0] = m;
        }
        __syncthreads();
        const float inv = 1.f / red_s[0];

        float2 x = make_float2(x0 * inv, x1 * inv);
        ((float2*)(out + (size_t)b * L))[tid] = x;
    }
}

// ---------------------------------------------------------------------------
extern "C" void kernel_launch(void* const* d_in, const int* in_sizes, int n_in,
                              void* d_out, int out_size) {
    const float* hidden  = (const float*)d_in[0];   // [1,B,H]
    const float* enc     = (const float*)d_in[1];   // [L,B,H]
    const float* W       = (const float*)d_in[2];   // [H,H]
    // d_in[3] = bias — provably cancels in softmax, unused
    const int*   lengths = (const int*)d_in[4];     // [B]
    float* out = (float*)d_out;                     // [B,1,L]

    fused_attn<<<NB, NT>>>(hidden, enc, W, lengths, out);
}

// round 15
// speedup vs baseline: 1.0752x; 1.0752x over previous
#include <cuda_runtime.h>

#define L 2048
#define B 32
#define H 1024
#define H4 256
#define NB 148
#define NT 1024
#define NITEMS (L / 2)   // 1024 items: l-pair x all b

// Scratch (allocation-free rule: __device__ globals)
__device__ float g_vpart[64][B][H];      // 8 MB partials (16 g each)
__device__ float g_vq[4][B][H];          // 512 KB quarter-reduced v
__device__ float g_v[B][H];              // 128 KB final v
__device__ float g_energy[B][L];         // 256 KB energies
__device__ unsigned g_maxu[B];           // monotone-encoded per-b max
__device__ unsigned g_bar;               // monotonic grid barrier counter
__device__ unsigned g_item;              // P3 block work counter

__device__ __forceinline__ unsigned enc_f(float x) {
    unsigned u = __float_as_uint(x);
    return (x >= 0.f) ? (u | 0x80000000u) : ~u;
}
__device__ __forceinline__ float dec_f(unsigned e) {
    return (e & 0x80000000u) ? __uint_as_float(e ^ 0x80000000u)
                             : __uint_as_float(~e);
}

// Software grid barrier: monotonic counter, no reset across replays.
__device__ __forceinline__ void grid_sync() {
    __syncthreads();
    if (threadIdx.x == 0) {
        __threadfence();
        const unsigned old = atomicAdd(&g_bar, 1u);
        const unsigned tgt = (old / NB + 1u) * NB;
        while (*(volatile unsigned*)&g_bar < tgt) __nanosleep(64);
        __threadfence();
    }
    __syncthreads();
}

__global__ void __launch_bounds__(NT, 1)
fused_attn(const float* __restrict__ hidden,
           const float* __restrict__ enc,
           const float* __restrict__ W,
           const int*   __restrict__ lengths,
           float* __restrict__ out) {
    const int tid = threadIdx.x;
    const int bid = blockIdx.x;

    __shared__ float hsh[4][4][16];      // P1 hidden stage (1 KB)
    __shared__ float red_s[32];          // P4 reduction
    __shared__ int   sh_item[2];         // double-buffered work broadcast

    if (bid == 0 && tid == 0) g_item = 0u;       // reset (pre-sync)
    if (bid == 0 && tid < B)  g_maxu[tid] = 0u;  // encoded -inf

    // ---------------- Phase 1: v partials ----------------
    // 512 groups = 64 g-slices x 8 b-quads; blocks 0..127, 4 groups each.
    if (bid < 128) {
        if (tid < 256) {   // stage hidden: 4 lg x 4 b x 16 g
            const int lg = tid >> 6, j = (tid >> 4) & 3, k = tid & 15;
            const int grp = bid * 4 + lg;
            const int gs = grp >> 3, bq = grp & 7;
            hsh[lg][j][k] = hidden[(size_t)(bq * 4 + j) * H + gs * 16 + k];
        }
        __syncthreads();

        const int lg = tid >> 8, hq = tid & 255;
        const int grp = bid * 4 + lg;
        const int gs = grp >> 3, bq = grp & 7;
        const int g0 = gs * 16, b0 = bq * 4;
        const float4* __restrict__ W4 = (const float4*)W;

        float4 acc[4];
        #pragma unroll
        for (int j = 0; j < 4; j++) acc[j] = make_float4(0.f, 0.f, 0.f, 0.f);

        #pragma unroll
        for (int r = 0; r < 4; r++) {
            float4 w[4];
            #pragma unroll
            for (int i = 0; i < 4; i++)
                w[i] = W4[(size_t)(g0 + r * 4 + i) * H4 + hq];
            #pragma unroll
            for (int i = 0; i < 4; i++) {
                #pragma unroll
                for (int j = 0; j < 4; j++) {
                    const float hv = hsh[lg][j][r * 4 + i];
                    acc[j].x += w[i].x * hv; acc[j].y += w[i].y * hv;
                    acc[j].z += w[i].z * hv; acc[j].w += w[i].w * hv;
                }
            }
        }
        #pragma unroll
        for (int j = 0; j < 4; j++)
            *(float4*)&g_vpart[gs][b0 + j][hq * 4] = acc[j];
    }
    grid_sync();

    // ---------------- Phase 2a: quarter reduce ----------------
    {
        const int t = bid * NT + tid;
        if (t < 32768) {
            const int q = t >> 13, f = t & 8191;
            const int b = f >> 8, h4 = f & 255;
            const int p0 = q * 16;
            float4 s = make_float4(0.f, 0.f, 0.f, 0.f);
            #pragma unroll
            for (int r = 0; r < 4; r++) {
                float4 v[4];
                #pragma unroll
                for (int i = 0; i < 4; i++)
                    v[i] = *(const float4*)&g_vpart[p0 + r * 4 + i][b][h4 * 4];
                #pragma unroll
                for (int i = 0; i < 4; i++) {
                    s.x += v[i].x; s.y += v[i].y; s.z += v[i].z; s.w += v[i].w;
                }
            }
            *(float4*)&g_vq[q][b][h4 * 4] = s;
        }
    }
    grid_sync();

    // ---------------- Phase 2b: final reduce -> g_v ----------------
    {
        const int t = bid * NT + tid;
        if (t < 8192) {
            const int b = t >> 8, h4 = t & 255;
            float4 v[4];
            #pragma unroll
            for (int q = 0; q < 4; q++)
                v[q] = *(const float4*)&g_vq[q][b][h4 * 4];
            float4 s = make_float4(v[0].x + v[1].x + v[2].x + v[3].x,
                                   v[0].y + v[1].y + v[2].y + v[3].y,
                                   v[0].z + v[1].z + v[2].z + v[3].z,
                                   v[0].w + v[1].w + v[2].w + v[3].w);
            *(float4*)&g_v[b][h4 * 4] = s;
        }
    }
    grid_sync();

    // ---------------- Phase 3: energies (l-major items, v in registers) ----
    // Item t = rows (2t, 2t+1) for ALL b: block reads 256 KB CONTIGUOUS.
    // Warp w <-> b=w fixed: v[b] lives in 8 float4 regs per lane, loaded once.
    // Rows l >= len[b] never read (exact: masked to 0 downstream). Block-level
    // stealing, one sync/item via double-buffered sh_item. Per-warp running
    // max -> single atomicMax at phase end.
    {
        const int warp = tid >> 5, lane = tid & 31;   // warp == b
        const float4* __restrict__ enc4 = (const float4*)enc;

        float4 vreg[8];
        #pragma unroll
        for (int kk = 0; kk < 8; kk++)
            vreg[kk] = *(const float4*)&g_v[warp][(kk * 32 + lane) * 4];
        const int mylen = lengths[warp];
        float wmax = -3.4e38f;

        int it = 0;
        for (;;) {
            if (tid == 0) sh_item[it & 1] = (int)atomicAdd(&g_item, 1u);
            __syncthreads();
            const int item = sh_item[it & 1];
            it++;
            if (item >= NITEMS) break;

            const int l0 = item * 2;
            if (l0 >= mylen) continue;        // warp-uniform skip (idle item)
            const bool v1 = (l0 + 1 < mylen);

            const size_t ba = ((size_t)l0 * B + warp) * H4;
            const size_t bb = ba + (size_t)B * H4;

            float a0 = 0.f, a1 = 0.f;
            if (v1) {
                #pragma unroll
                for (int kk = 0; kk < 8; kk++) {
                    const float4 e0 = __ldcs(&enc4[ba + kk * 32 + lane]);
                    const float4 e1 = __ldcs(&enc4[bb + kk * 32 + lane]);
                    a0 += e0.x * vreg[kk].x + e0.y * vreg[kk].y
                        + e0.z * vreg[kk].z + e0.w * vreg[kk].w;
                    a1 += e1.x * vreg[kk].x + e1.y * vreg[kk].y
                        + e1.z * vreg[kk].z + e1.w * vreg[kk].w;
                }
            } else {
                #pragma unroll
                for (int kk = 0; kk < 8; kk++) {
                    const float4 e0 = __ldcs(&enc4[ba + kk * 32 + lane]);
                    a0 += e0.x * vreg[kk].x + e0.y * vreg[kk].y
                        + e0.z * vreg[kk].z + e0.w * vreg[kk].w;
                }
            }
            #pragma unroll
            for (int s = 16; s; s >>= 1) {
                a0 += __shfl_down_sync(0xffffffffu, a0, s);
                a1 += __shfl_down_sync(0xffffffffu, a1, s);
            }
            if (lane == 0) {
                float m = a0;
                if (v1) {
                    *(float2*)&g_energy[warp][l0] = make_float2(a0, a1);
                    m = fmaxf(m, a1);
                } else {
                    g_energy[warp][l0] = a0;
                }
                wmax = fmaxf(wmax, m);
            }
        }
        if (lane == 0)
            atomicMax(&g_maxu[warp], enc_f(wmax));   // other blocks cover rest
    }
    grid_sync();

    // ---------------- Phase 4: masked softmax ----------------
    if (bid < B) {
        const int b   = bid;
        const int len = lengths[b];
        const int l0  = tid * 2;

        const float2 e = ((const float2*)&g_energy[b][0])[tid];
        const float mx = dec_f(g_maxu[b]);

        float x0 = (l0 + 0 < len) ? expf(e.x - mx) : 0.f;
        float x1 = (l0 + 1 < len) ? expf(e.y - mx) : 0.f;

        float sum = x0 + x1;
        #pragma unroll
        for (int s = 16; s; s >>= 1)
            sum += __shfl_xor_sync(0xffffffffu, sum, s);
        if ((tid & 31) == 0) red_s[tid >> 5] = sum;
        __syncthreads();
        if (tid < 32) {
            float m = red_s[tid];
            #pragma unroll
            for (int s = 16; s; s >>= 1)
                m += __shfl_xor_sync(0xffffffffu, m, s);
            if (tid == 0) red_s[0] = m;
        }
        __syncthreads();
        const float inv = 1.f / red_s[0];

        float2 x = make_float2(x0 * inv, x1 * inv);
        ((float2*)(out + (size_t)b * L))[tid] = x;
    }
}

// ---------------------------------------------------------------------------
extern "C" void kernel_launch(void* const* d_in, const int* in_sizes, int n_in,
                              void* d_out, int out_size) {
    const float* hidden  = (const float*)d_in[0];   // [1,B,H]
    const float* enc     = (const float*)d_in[1];   // [L,B,H]
    const float* W       = (const float*)d_in[2];   // [H,H]
    // d_in[3] = bias — provably cancels in softmax, unused
    const int*   lengths = (const int*)d_in[4];     // [B]
    float* out = (float*)d_out;                     // [B,1,L]

    fused_attn<<<NB, NT>>>(hidden, enc, W, lengths, out);
}

// round 16
// speedup vs baseline: 1.0823x; 1.0066x over previous
#include <cuda_runtime.h>

#define L 2048
#define B 32
#define H 1024
#define H4 256
#define NB 148
#define NT 1024

// Scratch (allocation-free rule: __device__ globals)
__device__ float g_vpart[64][B][H];      // 8 MB partials (16 g each)
__device__ float g_vq[4][B][H];          // 512 KB quarter-reduced v
__device__ float g_v[B][H];              // 128 KB final v (L1/L2-resident)
__device__ float g_energy[B][L];         // 256 KB energies
__device__ unsigned g_maxu[B];           // monotone-encoded per-b max
__device__ unsigned g_bar;               // monotonic grid barrier counter
__device__ unsigned g_item;              // P3 block work counter

__device__ __forceinline__ unsigned enc_f(float x) {
    unsigned u = __float_as_uint(x);
    return (x >= 0.f) ? (u | 0x80000000u) : ~u;
}
__device__ __forceinline__ float dec_f(unsigned e) {
    return (e & 0x80000000u) ? __uint_as_float(e ^ 0x80000000u)
                             : __uint_as_float(~e);
}

// Software grid barrier: monotonic counter, no reset across replays.
__device__ __forceinline__ void grid_sync() {
    __syncthreads();
    if (threadIdx.x == 0) {
        __threadfence();
        const unsigned old = atomicAdd(&g_bar, 1u);
        const unsigned tgt = (old / NB + 1u) * NB;
        while (*(volatile unsigned*)&g_bar < tgt) __nanosleep(64);
        __threadfence();
    }
    __syncthreads();
}

__global__ void __launch_bounds__(NT, 1)
fused_attn(const float* __restrict__ hidden,
           const float* __restrict__ enc,
           const float* __restrict__ W,
           const int*   __restrict__ lengths,
           float* __restrict__ out) {
    const int tid = threadIdx.x;
    const int bid = blockIdx.x;

    __shared__ float hsh[4][4][16];      // P1 hidden stage (1 KB)
    __shared__ float red_s[32];          // P4 reduction
    __shared__ int   sh_item[2];         // double-buffered work broadcast

    if (bid == 0 && tid == 0) g_item = 0u;       // reset (pre-sync)
    if (bid == 0 && tid < B)  g_maxu[tid] = 0u;  // encoded -inf

    // ---------------- Phase 1: v partials ----------------
    // 512 groups = 64 g-slices x 8 b-quads; blocks 0..127, 4 groups each.
    if (bid < 128) {
        if (tid < 256) {   // stage hidden: 4 lg x 4 b x 16 g
            const int lg = tid >> 6, j = (tid >> 4) & 3, k = tid & 15;
            const int grp = bid * 4 + lg;
            const int gs = grp >> 3, bq = grp & 7;
            hsh[lg][j][k] = hidden[(size_t)(bq * 4 + j) * H + gs * 16 + k];
        }
        __syncthreads();

        const int lg = tid >> 8, hq = tid & 255;
        const int grp = bid * 4 + lg;
        const int gs = grp >> 3, bq = grp & 7;
        const int g0 = gs * 16, b0 = bq * 4;
        const float4* __restrict__ W4 = (const float4*)W;

        float4 acc[4];
        #pragma unroll
        for (int j = 0; j < 4; j++) acc[j] = make_float4(0.f, 0.f, 0.f, 0.f);

        #pragma unroll
        for (int r = 0; r < 4; r++) {
            float4 w[4];
            #pragma unroll
            for (int i = 0; i < 4; i++)
                w[i] = W4[(size_t)(g0 + r * 4 + i) * H4 + hq];
            #pragma unroll
            for (int i = 0; i < 4; i++) {
                #pragma unroll
                for (int j = 0; j < 4; j++) {
                    const float hv = hsh[lg][j][r * 4 + i];
                    acc[j].x += w[i].x * hv; acc[j].y += w[i].y * hv;
                    acc[j].z += w[i].z * hv; acc[j].w += w[i].w * hv;
                }
            }
        }
        #pragma unroll
        for (int j = 0; j < 4; j++)
            *(float4*)&g_vpart[gs][b0 + j][hq * 4] = acc[j];
    }
    grid_sync();

    // ---------------- Phase 2a: quarter reduce ----------------
    {
        const int t = bid * NT + tid;
        if (t < 32768) {
            const int q = t >> 13, f = t & 8191;
            const int b = f >> 8, h4 = f & 255;
            const int p0 = q * 16;
            float4 s = make_float4(0.f, 0.f, 0.f, 0.f);
            #pragma unroll
            for (int r = 0; r < 4; r++) {
                float4 v[4];
                #pragma unroll
                for (int i = 0; i < 4; i++)
                    v[i] = *(const float4*)&g_vpart[p0 + r * 4 + i][b][h4 * 4];
                #pragma unroll
                for (int i = 0; i < 4; i++) {
                    s.x += v[i].x; s.y += v[i].y; s.z += v[i].z; s.w += v[i].w;
                }
            }
            *(float4*)&g_vq[q][b][h4 * 4] = s;
        }
    }
    grid_sync();

    // ---------------- Phase 2b: final reduce -> g_v ----------------
    {
        const int t = bid * NT + tid;
        if (t < 8192) {
            const int b = t >> 8, h4 = t & 255;
            float4 v[4];
            #pragma unroll
            for (int q = 0; q < 4; q++)
                v[q] = *(const float4*)&g_vq[q][b][h4 * 4];
            float4 s = make_float4(v[0].x + v[1].x + v[2].x + v[3].x,
                                   v[0].y + v[1].y + v[2].y + v[3].y,
                                   v[0].z + v[1].z + v[2].z + v[3].z,
                                   v[0].w + v[1].w + v[2].w + v[3].w);
            *(float4*)&g_v[b][h4 * 4] = s;
        }
    }
    grid_sync();

    // ---------------- Phase 3: energies (dense valid-pair enumeration) ----
    // Valid l-pairs enumerated b-major: u in [0, tot), tot = sum ceil(len/2).
    // u -> b via one ballot over lane-cached exclusive prefix; l0 = 2(u-cum[b]).
    // EVERY item keeps all 32 warps on valid rows (no activity decay), rows
    // l >= len[b] never read (exact: masked to 0 downstream). Block-level
    // stealing, one sync/item (double-buffered sh_item). v cached in regs,
    // reloaded only on b-change; per-warp max flushed on b-change / at end.
    {
        const int warp = tid >> 5, lane = tid & 31;
        const float4* __restrict__ enc4 = (const float4*)enc;

        const int mylen = lengths[lane];          // b = lane
        int x = (mylen + 1) >> 1;                 // nv[b]
        #pragma unroll
        for (int d = 1; d < 32; d <<= 1) {        // inclusive scan
            const int y = __shfl_up_sync(0xffffffffu, x, d);
            if (lane >= d) x += y;
        }
        const int tot   = __shfl_sync(0xffffffffu, x, 31);
        const int cumex = x - ((mylen + 1) >> 1); // exclusive prefix (lane=b)

        float4 vreg[8];
        int curb = -1;
        float wmax = -3.4e38f;

        int it = 0;
        for (;;) {
            if (tid == 0) sh_item[it & 1] = (int)atomicAdd(&g_item, 1u);
            __syncthreads();
            const int item = sh_item[it & 1];
            it++;
            if (item * 32 >= tot) break;

            const int u = item * 32 + warp;       // warp-uniform
            if (u >= tot) continue;               // only final partial item

            const unsigned bal = __ballot_sync(0xffffffffu, cumex <= u);
            const int b     = __popc(bal) - 1;
            const int cum_b = __shfl_sync(0xffffffffu, cumex, b);
            const int len_b = __shfl_sync(0xffffffffu, mylen, b);
            const int l0    = (u - cum_b) * 2;
            const bool v1   = (l0 + 1 < len_b);

            if (b != curb) {                      // rare: reload v, flush max
                if (lane == 0 && curb >= 0)
                    atomicMax(&g_maxu[curb], enc_f(wmax));
                wmax = -3.4e38f;
                curb = b;
                #pragma unroll
                for (int kk = 0; kk < 8; kk++)
                    vreg[kk] = *(const float4*)&g_v[b][(kk * 32 + lane) * 4];
            }

            const size_t ba = ((size_t)l0 * B + b) * H4;
            const size_t bb = ba + (size_t)B * H4;

            float a0 = 0.f, a1 = 0.f;
            if (v1) {
                #pragma unroll
                for (int kk = 0; kk < 8; kk++) {
                    const float4 e0 = __ldcs(&enc4[ba + kk * 32 + lane]);
                    const float4 e1 = __ldcs(&enc4[bb + kk * 32 + lane]);
                    a0 += e0.x * vreg[kk].x + e0.y * vreg[kk].y
                        + e0.z * vreg[kk].z + e0.w * vreg[kk].w;
                    a1 += e1.x * vreg[kk].x + e1.y * vreg[kk].y
                        + e1.z * vreg[kk].z + e1.w * vreg[kk].w;
                }
            } else {
                #pragma unroll
                for (int kk = 0; kk < 8; kk++) {
                    const float4 e0 = __ldcs(&enc4[ba + kk * 32 + lane]);
                    a0 += e0.x * vreg[kk].x + e0.y * vreg[kk].y
                        + e0.z * vreg[kk].z + e0.w * vreg[kk].w;
                }
            }
            #pragma unroll
            for (int s = 16; s; s >>= 1) {
                a0 += __shfl_down_sync(0xffffffffu, a0, s);
                a1 += __shfl_down_sync(0xffffffffu, a1, s);
            }
            if (lane == 0) {
                float m = a0;
                if (v1) {
                    *(float2*)&g_energy[b][l0] = make_float2(a0, a1);
                    m = fmaxf(m, a1);
                } else {
                    g_energy[b][l0] = a0;
                }
                wmax = fmaxf(wmax, m);
            }
        }
        if (lane == 0 && curb >= 0)
            atomicMax(&g_maxu[curb], enc_f(wmax));   // final flush
    }
    grid_sync();

    // ---------------- Phase 4: masked softmax ----------------
    if (bid < B) {
        const int b   = bid;
        const int len = lengths[b];
        const int l0  = tid * 2;

        const float2 e = ((const float2*)&g_energy[b][0])[tid];
        const float mx = dec_f(g_maxu[b]);

        float x0 = (l0 + 0 < len) ? expf(e.x - mx) : 0.f;
        float x1 = (l0 + 1 < len) ? expf(e.y - mx) : 0.f;

        float sum = x0 + x1;
        #pragma unroll
        for (int s = 16; s; s >>= 1)
            sum += __shfl_xor_sync(0xffffffffu, sum, s);
        if ((tid & 31) == 0) red_s[tid >> 5] = sum;
        __syncthreads();
        if (tid < 32) {
            float m = red_s[tid];
            #pragma unroll
            for (int s = 16; s; s >>= 1)
                m += __shfl_xor_sync(0xffffffffu, m, s);
            if (tid == 0) red_s[0] = m;
        }
        __syncthreads();
        const float inv = 1.f / red_s[0];

        float2 x = make_float2(x0 * inv, x1 * inv);
        ((float2*)(out + (size_t)b * L))[tid] = x;
    }
}

// ---------------------------------------------------------------------------
extern "C" void kernel_launch(void* const* d_in, const int* in_sizes, int n_in,
                              void* d_out, int out_size) {
    const float* hidden  = (const float*)d_in[0];   // [1,B,H]
    const float* enc     = (const float*)d_in[1];   // [L,B,H]
    const float* W       = (const float*)d_in[2];   // [H,H]
    // d_in[3] = bias — provably cancels in softmax, unused
    const int*   lengths = (const int*)d_in[4];     // [B]
    float* out = (float*)d_out;                     // [B,1,L]

    fused_attn<<<NB, NT>>>(hidden, enc, W, lengths, out);
}

// round 17
// speedup vs baseline: 1.2214x; 1.1285x over previous
#include <cuda_runtime.h>

#define L 2048
#define B 32
#define H 1024
#define H4 256
#define NB 148
#define NT 1024
#define PF_BLOCKS 84          // prefetch blocks 64..147
#define PF_ITER 18            // ~25 MB of enc into L2

// Scratch (allocation-free rule: __device__ globals)
__device__ float g_v[B][H];              // 128 KB final v (L1/L2-resident)
__device__ float g_energy[B][L];         // 256 KB energies
__device__ float g_scratch[PF_BLOCKS * 32];  // prefetch sink (never read)
__device__ unsigned g_maxu[B];           // monotone-encoded per-b max
__device__ unsigned g_bar;               // monotonic grid barrier counter
__device__ unsigned g_item;              // P3 block work counter

__device__ __forceinline__ unsigned enc_f(float x) {
    unsigned u = __float_as_uint(x);
    return (x >= 0.f) ? (u | 0x80000000u) : ~u;
}
__device__ __forceinline__ float dec_f(unsigned e) {
    return (e & 0x80000000u) ? __uint_as_float(e ^ 0x80000000u)
                             : __uint_as_float(~e);
}

// Software grid barrier: monotonic counter, no reset across replays.
__device__ __forceinline__ void grid_sync() {
    __syncthreads();
    if (threadIdx.x == 0) {
        __threadfence();
        const unsigned old = atomicAdd(&g_bar, 1u);
        const unsigned tgt = (old / NB + 1u) * NB;
        while (*(volatile unsigned*)&g_bar < tgt) __nanosleep(64);
        __threadfence();
    }
    __syncthreads();
}

__global__ void __launch_bounds__(NT, 1)
fused_attn(const float* __restrict__ hidden,
           const float* __restrict__ enc,
           const float* __restrict__ W,
           const int*   __restrict__ lengths,
           float* __restrict__ out) {
    const int tid = threadIdx.x;
    const int bid = blockIdx.x;

    __shared__ float  hsh[4][H];         // P1 hidden rows (16 KB)
    __shared__ float4 buf[8][4][32];     // P1 slice-reduction (16 KB)
    __shared__ float  red_s[32];         // P4 reduction
    __shared__ int    sh_item[2];        // double-buffered work broadcast

    if (bid == 0 && tid == 0) g_item = 0u;       // reset (pre-sync)
    if (bid == 0 && tid < B)  g_maxu[tid] = 0u;  // encoded -inf

    // ---------------- Phase 1: v = hidden @ W (direct, in-block reduce) ----
    // Blocks 0..63: (htile 0..7) x (bq 0..7). 1024 thr = 32 g-slices x 32 hq.
    // Thread: 32 W float4 loads (8-deep batches), 4 b accumulators.
    // Slice reduction: 4 waves into buf, then 128 threads write g_v.
    if (bid < 64) {
        const int htile = bid & 7;
        const int bq    = bid >> 3;
        const int b0    = bq * 4;
        const int s     = tid >> 5;                 // g-slice (warp)
        const int lane  = tid & 31;
        const int hq    = htile * 32 + lane;        // float4 column
        const int g0    = s * 32;

        {   // stage hidden[b0..b0+4) : 1024 float4, one per thread
            const int bb = tid >> 8, g4 = tid & 255;
            ((float4*)hsh[bb])[g4] =
                ((const float4*)hidden)[(size_t)(b0 + bb) * H4 + g4];
        }
        __syncthreads();

        const float4* __restrict__ W4 = (const float4*)W;
        float4 acc[4];
        #pragma unroll
        for (int j = 0; j < 4; j++) acc[j] = make_float4(0.f, 0.f, 0.f, 0.f);

        #pragma unroll
        for (int r = 0; r < 4; r++) {
            float4 w[8];                            // 8 loads in flight
            #pragma unroll
            for (int i = 0; i < 8; i++)
                w[i] = W4[(size_t)(g0 + r * 8 + i) * H4 + hq];
            #pragma unroll
            for (int i = 0; i < 8; i++) {
                #pragma unroll
                for (int j = 0; j < 4; j++) {
                    const float hv = hsh[j][g0 + r * 8 + i];  // broadcast
                    acc[j].x += w[i].x * hv; acc[j].y += w[i].y * hv;
                    acc[j].z += w[i].z * hv; acc[j].w += w[i].w * hv;
                }
            }
        }

        // 4-wave slice reduction into buf[8][4][32]
        if (s < 8) {
            #pragma unroll
            for (int j = 0; j < 4; j++) buf[s][j][lane] = acc[j];
        }
        __syncthreads();
        #pragma unroll
        for (int wv = 1; wv < 4; wv++) {
            if ((s >> 3) == wv) {
                #pragma unroll
                for (int j = 0; j < 4; j++) {
                    float4 t = buf[s & 7][j][lane];
                    t.x += acc[j].x; t.y += acc[j].y;
                    t.z += acc[j].z; t.w += acc[j].w;
                    buf[s & 7][j][lane] = t;
                }
            }
            __syncthreads();
        }
        if (tid < 128) {                            // final 8-way sum -> g_v
            const int j = tid >> 5, ln = tid & 31;
            float4 sm = make_float4(0.f, 0.f, 0.f, 0.f);
            #pragma unroll
            for (int p = 0; p < 8; p++) {
                const float4 t = buf[p][j][ln];
                sm.x += t.x; sm.y += t.y; sm.z += t.z; sm.w += t.w;
            }
            *(float4*)&g_v[b0 + j][(htile * 32 + ln) * 4] = sm;
        }
    } else {
        // ---------------- Prefetch: blocks 64..147 warm L2 with enc head ----
        // ~25 MB via __ldcg; P3's __ldcs streams are evict-first so these
        // lines survive until consumed. Sink store defeats load elision.
        const float4* __restrict__ enc4 = (const float4*)enc;
        const size_t base = (size_t)(bid - 64) * NT + tid;
        float s = 0.f;
        #pragma unroll
        for (int i = 0; i < PF_ITER; i++) {
            const float4 v = __ldcg(&enc4[base + (size_t)i * (PF_BLOCKS * NT)]);
            s += v.x + v.y + v.z + v.w;
        }
        #pragma unroll
        for (int d = 16; d; d >>= 1)
            s += __shfl_down_sync(0xffffffffu, s, d);
        if ((tid & 31) == 0)
            g_scratch[(bid - 64) * 32 + (tid >> 5)] = s;   // never read
    }
    grid_sync();

    // ---------------- Phase 3: energies (dense valid-pair enumeration) ----
    // Valid l-pairs enumerated b-major: u in [0, tot), tot = sum ceil(len/2).
    // u -> b via one ballot over lane-cached exclusive prefix; l0 = 2(u-cum[b]).
    // Every item keeps all 32 warps on valid rows; rows l >= len[b] never
    // read (exact: masked to 0 downstream). Block-level stealing, one sync
    // per item (double-buffered sh_item). v cached in regs, reloaded on
    // b-change; per-warp max flushed on b-change / at end.
    {
        const int warp = tid >> 5, lane = tid & 31;
        const float4* __restrict__ enc4 = (const float4*)enc;

        const int mylen = lengths[lane];          // b = lane
        int x = (mylen + 1) >> 1;                 // nv[b]
        #pragma unroll
        for (int d = 1; d < 32; d <<= 1) {        // inclusive scan
            const int y = __shfl_up_sync(0xffffffffu, x, d);
            if (lane >= d) x += y;
        }
        const int tot   = __shfl_sync(0xffffffffu, x, 31);
        const int cumex = x - ((mylen + 1) >> 1); // exclusive prefix (lane=b)

        float4 vreg[8];
        int curb = -1;
        float wmax = -3.4e38f;

        int it = 0;
        for (;;) {
            if (tid == 0) sh_item[it & 1] = (int)atomicAdd(&g_item, 1u);
            __syncthreads();
            const int item = sh_item[it & 1];
            it++;
            if (item * 32 >= tot) break;

            const int u = item * 32 + warp;       // warp-uniform
            if (u >= tot) continue;               // only final partial item

            const unsigned bal = __ballot_sync(0xffffffffu, cumex <= u);
            const int b     = __popc(bal) - 1;
            const int cum_b = __shfl_sync(0xffffffffu, cumex, b);
            const int len_b = __shfl_sync(0xffffffffu, mylen, b);
            const int l0    = (u - cum_b) * 2;
            const bool v1   = (l0 + 1 < len_b);

            if (b != curb) {                      // rare: reload v, flush max
                if (lane == 0 && curb >= 0)
                    atomicMax(&g_maxu[curb], enc_f(wmax));
                wmax = -3.4e38f;
                curb = b;
                #pragma unroll
                for (int kk = 0; kk < 8; kk++)
                    vreg[kk] = *(const float4*)&g_v[b][(kk * 32 + lane) * 4];
            }

            const size_t ba = ((size_t)l0 * B + b) * H4;
            const size_t bb = ba + (size_t)B * H4;

            float a0 = 0.f, a1 = 0.f;
            if (v1) {
                #pragma unroll
                for (int kk = 0; kk < 8; kk++) {
                    const float4 e0 = __ldcs(&enc4[ba + kk * 32 + lane]);
                    const float4 e1 = __ldcs(&enc4[bb + kk * 32 + lane]);
                    a0 += e0.x * vreg[kk].x + e0.y * vreg[kk].y
                        + e0.z * vreg[kk].z + e0.w * vreg[kk].w;
                    a1 += e1.x * vreg[kk].x + e1.y * vreg[kk].y
                        + e1.z * vreg[kk].z + e1.w * vreg[kk].w;
                }
            } else {
                #pragma unroll
                for (int kk = 0; kk < 8; kk++) {
                    const float4 e0 = __ldcs(&enc4[ba + kk * 32 + lane]);
                    a0 += e0.x * vreg[kk].x + e0.y * vreg[kk].y
                        + e0.z * vreg[kk].z + e0.w * vreg[kk].w;
                }
            }
            #pragma unroll
            for (int s = 16; s; s >>= 1) {
                a0 += __shfl_down_sync(0xffffffffu, a0, s);
                a1 += __shfl_down_sync(0xffffffffu, a1, s);
            }
            if (lane == 0) {
                float m = a0;
                if (v1) {
                    *(float2*)&g_energy[b][l0] = make_float2(a0, a1);
                    m = fmaxf(m, a1);
                } else {
                    g_energy[b][l0] = a0;
                }
                wmax = fmaxf(wmax, m);
            }
        }
        if (lane == 0 && curb >= 0)
            atomicMax(&g_maxu[curb], enc_f(wmax));   // final flush
    }
    grid_sync();

    // ---------------- Phase 4: masked softmax ----------------
    if (bid < B) {
        const int b   = bid;
        const int len = lengths[b];
        const int l0  = tid * 2;

        const float2 e = ((const float2*)&g_energy[b][0])[tid];
        const float mx = dec_f(g_maxu[b]);

        float x0 = (l0 + 0 < len) ? expf(e.x - mx) : 0.f;
        float x1 = (l0 + 1 < len) ? expf(e.y - mx) : 0.f;

        float sum = x0 + x1;
        #pragma unroll
        for (int s = 16; s; s >>= 1)
            sum += __shfl_xor_sync(0xffffffffu, sum, s);
        if ((tid & 31) == 0) red_s[tid >> 5] = sum;
        __syncthreads();
        if (tid < 32) {
            float m = red_s[tid];
            #pragma unroll
            for (int s = 16; s; s >>= 1)
                m += __shfl_xor_sync(0xffffffffu, m, s);
            if (tid == 0) red_s[0] = m;
        }
        __syncthreads();
        const float inv = 1.f / red_s[0];

        float2 x = make_float2(x0 * inv, x1 * inv);
        ((float2*)(out + (size_t)b * L))[tid] = x;
    }
}

// ---------------------------------------------------------------------------
extern "C" void kernel_launch(void* const* d_in, const int* in_sizes, int n_in,
                              void* d_out, int out_size) {
    const float* hidden  = (const float*)d_in[0];   // [1,B,H]
    const float* enc     = (const float*)d_in[1];   // [L,B,H]
    const float* W       = (const float*)d_in[2];   // [H,H]
    // d_in[3] = bias — provably cancels in softmax, unused
    const int*   lengths = (const int*)d_in[4];     // [B]
    float* out = (float*)d_out;                     // [B,1,L]

    fused_attn<<<NB, NT>>>(hidden, enc, W, lengths, out);
}